// round 7
// baseline (speedup 1.0000x reference)
#include <cuda_runtime.h>
#include <cstdint>

// ---------------------------------------------------------------------------
// SNN multi-layer LIF with feedback. B=512, D=2048, L=3, T=16.
// Bitwise-exact fp32, chunk-512 blocked-K accumulation (verified R4/R5).
// Round 7: R6 design with the smem overflow fixed — the last-arrival flag is
// aliased onto As2 (dead after the mainloop) instead of its own __shared__.
// Fused GEMM + (last CTA) ordered reduce + LIF epilogue; cp.async B tiles.
// ---------------------------------------------------------------------------

#define Bsz 512
#define Dd  2048
#define NL  3
#define TSTEPS 16
#define DD (Dd * Dd)
#define BD (Bsz * Dd)
#define NCHUNK 4
#define KCHUNK 512
#define NTILES 64          // (Dd/128) * (Bsz/128)

__device__ float g_x1[BD];
__device__ float g_u[NL][BD];
__device__ float g_s[NL][BD];
__device__ float g_af[BD];
__device__ float g_al[BD];
__device__ float g_part[NCHUNK][BD];
__device__ int   g_cnt[NTILES];    // zero-init; reset by last CTA each stage

#define VTH 1.0f
#define LK  0.9f
// (1 - 0.9^16) / (1 - 0.9) rounded to f32
#define WEIGHTED 8.146979811148159f

__device__ __forceinline__ uint64_t ffma2(uint64_t a, uint64_t b, uint64_t c) {
    uint64_t d;
    asm("fma.rn.f32x2 %0, %1, %2, %3;" : "=l"(d) : "l"(a), "l"(b), "l"(c));
    return d;
}
__device__ __forceinline__ void lds_pair(uint32_t addr, uint64_t& p0, uint64_t& p1) {
    asm volatile("ld.shared.v2.b64 {%0, %1}, [%2];" : "=l"(p0), "=l"(p1) : "r"(addr));
}
__device__ __forceinline__ void unpack2(uint64_t p, float& lo, float& hi) {
    asm("mov.b64 {%0, %1}, %2;" : "=f"(lo), "=f"(hi) : "l"(p));
}
__device__ __forceinline__ void cp16(uint32_t s, const void* g) {
    asm volatile("cp.async.ca.shared.global [%0], [%1], 16;" :: "r"(s), "l"(g));
}
#define CP_COMMIT() asm volatile("cp.async.commit_group;")
#define CP_WAIT0()  asm volatile("cp.async.wait_group 0;")

// ---------------------------------------------------------------------------
// Fused GEMM-chunk + (last CTA) reduce + LIF epilogue.
// BM=BN=128, BK=16, 256 threads, 8x8 micro-tile via packed f32x2 FMA.
// ---------------------------------------------------------------------------
template<bool ADD_UPREV, bool ADD_X1, bool WRITE_RAW, int ACCM>
__global__ __launch_bounds__(256, 2)
void gemm_lif_fused(const float* __restrict__ Aext,
                    const float* __restrict__ W,
                    const float* __restrict__ bias,
                    int a_sel, int layer,
                    float* __restrict__ finout)
{
    const float* __restrict__ A = (a_sel < 0) ? Aext : g_s[a_sel];

    // As2: A duplicated: As2[k][2m] = As2[k][2m+1] = A[m][k]
    __shared__ float As2[2][16][256];   // 32 KB
    __shared__ float Bs[2][16][128];    // 16 KB  (total = 48 KB exactly)

    const int tid = threadIdx.x;
    const int bn0 = blockIdx.x * 128;
    const int bm0 = blockIdx.y * 128;
    const int myz = blockIdx.z;
    const int k0  = myz * KCHUNK;
    const int tile = blockIdx.y * gridDim.x + blockIdx.x;

    // A loader: 128 rows x 16 k; 2 float4 per thread
    const int ar = tid >> 1;            // 0..127
    const int ac = (tid & 1) << 3;      // 0 or 8
    // B loader: 16 k-rows x 128 n; 2 x 16B cp.async per thread
    const int wr = tid >> 4;            // 0..15
    const int wc = (tid & 15) << 3;     // 0..120

    const float* __restrict__ Ap = A + (size_t)(bm0 + ar) * Dd + (k0 + ac);
    const float* __restrict__ Wp = W + (size_t)(k0 + wr) * Dd + (bn0 + wc);

    const uint32_t sBw0 = (uint32_t)__cvta_generic_to_shared(&Bs[0][wr][wc]);
    const uint32_t sBw1 = sBw0 + 16;
    const uint32_t B_BUF = 16 * 128 * 4;

    // prime buffer 0
    {
        cp16(sBw0, Wp);
        cp16(sBw1, Wp + 4);
        CP_COMMIT();
        float4 a0 = *(const float4*)Ap;
        float4 a1 = *(const float4*)(Ap + 4);
        float av[8] = {a0.x, a0.y, a0.z, a0.w, a1.x, a1.y, a1.z, a1.w};
        #pragma unroll
        for (int i = 0; i < 8; ++i)
            *(float2*)&As2[0][ac + i][2 * ar] = make_float2(av[i], av[i]);
        CP_WAIT0();
    }
    __syncthreads();

    const int tx = tid & 15;            // n group
    const int ty = tid >> 4;            // m group
    const int rn = tx << 3;             // 0..120
    const int rm = ty << 3;             // 0..120

    const uint32_t sA = (uint32_t)__cvta_generic_to_shared(&As2[0][0][0]) + rm * 8;
    const uint32_t sB = (uint32_t)__cvta_generic_to_shared(&Bs[0][0][0])  + rn * 4;
    const uint32_t A_BUF = 16 * 256 * 4;

    uint64_t acc[8][4];
    #pragma unroll
    for (int i = 0; i < 8; ++i)
        #pragma unroll
        for (int j = 0; j < 4; ++j) acc[i][j] = 0ull;

    const int NT = KCHUNK / 16;         // 32 K-tiles
    #pragma unroll 1
    for (int t = 0; t < NT; ++t) {
        const int cur = t & 1;
        const bool more = (t + 1 < NT);

        float4 a0, a1;
        if (more) {
            const int nb = (t + 1) & 1;
            const float* Wp2 = Wp + (size_t)(t + 1) * 16 * Dd;
            cp16(sBw0 + nb * B_BUF, Wp2);
            cp16(sBw1 + nb * B_BUF, Wp2 + 4);
            CP_COMMIT();
            const float* Ap2 = Ap + (t + 1) * 16;
            a0 = *(const float4*)Ap2;
            a1 = *(const float4*)(Ap2 + 4);
        }

        const uint32_t baseA = sA + cur * A_BUF;
        const uint32_t baseB = sB + cur * B_BUF;

        #pragma unroll
        for (int kk = 0; kk < 16; ++kk) {
            uint64_t ap[8], bp[4];
            lds_pair(baseA + kk * 1024 +  0, ap[0], ap[1]);
            lds_pair(baseA + kk * 1024 + 16, ap[2], ap[3]);
            lds_pair(baseA + kk * 1024 + 32, ap[4], ap[5]);
            lds_pair(baseA + kk * 1024 + 48, ap[6], ap[7]);
            lds_pair(baseB + kk * 512  +  0, bp[0], bp[1]);
            lds_pair(baseB + kk * 512  + 16, bp[2], bp[3]);
            #pragma unroll
            for (int i = 0; i < 8; ++i)
                #pragma unroll
                for (int j = 0; j < 4; ++j)
                    acc[i][j] = ffma2(ap[i], bp[j], acc[i][j]);
        }

        if (more) {
            const int nb = (t + 1) & 1;
            float av[8] = {a0.x, a0.y, a0.z, a0.w, a1.x, a1.y, a1.z, a1.w};
            #pragma unroll
            for (int i = 0; i < 8; ++i)
                *(float2*)&As2[nb][ac + i][2 * ar] = make_float2(av[i], av[i]);
            CP_WAIT0();
            __syncthreads();
        }
    }

    // ---- write this chunk's partial
    float* __restrict__ P = g_part[myz];
    #pragma unroll
    for (int i = 0; i < 8; ++i) {
        float o[8];
        unpack2(acc[i][0], o[0], o[1]);
        unpack2(acc[i][1], o[2], o[3]);
        unpack2(acc[i][2], o[4], o[5]);
        unpack2(acc[i][3], o[6], o[7]);
        const size_t idx = (size_t)(bm0 + rm + i) * Dd + (bn0 + rn);
        *(float4*)&P[idx]     = make_float4(o[0], o[1], o[2], o[3]);
        *(float4*)&P[idx + 4] = make_float4(o[4], o[5], o[6], o[7]);
    }

    // ---- last-arrival detection (flag aliased onto dead As2 smem)
    volatile int* s_last = (volatile int*)&As2[0][0][0];
    __threadfence();
    __syncthreads();                    // all lanes done reading As2/Bs
    if (tid == 0) {
        int old = atomicAdd(&g_cnt[tile], 1);
        *s_last = (old == NCHUNK - 1) ? 1 : 0;
    }
    __syncthreads();
    if (!*s_last) return;
    if (tid == 0) g_cnt[tile] = 0;      // reset for next stage (next launch)
    __threadfence();                    // acquire other chunks' partials

    // ---- fold partials (ascending chunk order; own chunk from registers)
    // then exact R5 epilogue.
    float* __restrict__ u_out = g_u[layer];
    float* __restrict__ s_out = g_s[layer];
    float* __restrict__ accb  = (layer == 0) ? g_af : g_al;

    float bb[8];
    #pragma unroll
    for (int j = 0; j < 8; ++j) bb[j] = bias[bn0 + rn + j];

    #pragma unroll 1
    for (int i = 0; i < 8; ++i) {
        const size_t idx = (size_t)(bm0 + rm + i) * Dd + (bn0 + rn);

        float own[8];
        unpack2(acc[i][0], own[0], own[1]);
        unpack2(acc[i][1], own[2], own[3]);
        unpack2(acc[i][2], own[4], own[5]);
        unpack2(acc[i][3], own[6], own[7]);

        float v[8];
        // z = 0
        if (myz == 0) {
            #pragma unroll
            for (int j = 0; j < 8; ++j) v[j] = own[j];
        } else {
            float4 p0 = *(const float4*)&g_part[0][idx];
            float4 p1 = *(const float4*)&g_part[0][idx + 4];
            v[0] = p0.x; v[1] = p0.y; v[2] = p0.z; v[3] = p0.w;
            v[4] = p1.x; v[5] = p1.y; v[6] = p1.z; v[7] = p1.w;
        }
        // z = 1..3 ascending
        #pragma unroll
        for (int z = 1; z < NCHUNK; ++z) {
            if (myz == z) {
                #pragma unroll
                for (int j = 0; j < 8; ++j) v[j] = __fadd_rn(v[j], own[j]);
            } else {
                float4 p0 = *(const float4*)&g_part[z][idx];
                float4 p1 = *(const float4*)&g_part[z][idx + 4];
                float pv[8] = {p0.x, p0.y, p0.z, p0.w, p1.x, p1.y, p1.z, p1.w};
                #pragma unroll
                for (int j = 0; j < 8; ++j) v[j] = __fadd_rn(v[j], pv[j]);
            }
        }

        float uo[8], x1v[8], ab[8];
        if (ADD_UPREV) {
            float4 q0 = *(const float4*)&u_out[idx];
            float4 q1 = *(const float4*)&u_out[idx + 4];
            uo[0]=q0.x; uo[1]=q0.y; uo[2]=q0.z; uo[3]=q0.w;
            uo[4]=q1.x; uo[5]=q1.y; uo[6]=q1.z; uo[7]=q1.w;
        }
        if (ADD_X1) {
            float4 q0 = *(const float4*)&g_x1[idx];
            float4 q1 = *(const float4*)&g_x1[idx + 4];
            x1v[0]=q0.x; x1v[1]=q0.y; x1v[2]=q0.z; x1v[3]=q0.w;
            x1v[4]=q1.x; x1v[5]=q1.y; x1v[6]=q1.z; x1v[7]=q1.w;
        }
        if (ACCM == 2 || ACCM == 3) {
            float4 q0 = *(const float4*)&accb[idx];
            float4 q1 = *(const float4*)&accb[idx + 4];
            ab[0]=q0.x; ab[1]=q0.y; ab[2]=q0.z; ab[3]=q0.w;
            ab[4]=q1.x; ab[5]=q1.y; ab[6]=q1.z; ab[7]=q1.w;
        }

        float un[8], sp[8], ao[8], fo[8];
        #pragma unroll
        for (int j = 0; j < 8; ++j) {
            float w = v[j];
            if (ADD_UPREV) w = __fadd_rn(uo[j], w);    // u_prev + dot
            w = __fadd_rn(w, bb[j]);                   // + bias
            if (ADD_X1)    w = __fadd_rn(w, x1v[j]);   // + x1
            if (WRITE_RAW) x1v[j] = w;                 // stash x1

            float s = (w >= VTH) ? 1.0f : 0.0f;
            un[j] = __fmul_rn(__fsub_rn(w, s), LK);
            sp[j] = s;

            if (ACCM == 1) {
                ao[j] = s;
            } else if (ACCM == 2) {
                ao[j] = __fadd_rn(__fmul_rn(ab[j], LK), s);
            } else if (ACCM == 3) {
                float a2 = __fadd_rn(__fmul_rn(ab[j], LK), s);
                fo[j] = __fdiv_rn(a2, WEIGHTED);
            }
        }

        *(float4*)&u_out[idx]     = make_float4(un[0], un[1], un[2], un[3]);
        *(float4*)&u_out[idx + 4] = make_float4(un[4], un[5], un[6], un[7]);
        *(float4*)&s_out[idx]     = make_float4(sp[0], sp[1], sp[2], sp[3]);
        *(float4*)&s_out[idx + 4] = make_float4(sp[4], sp[5], sp[6], sp[7]);
        if (WRITE_RAW) {
            *(float4*)&g_x1[idx]     = make_float4(x1v[0], x1v[1], x1v[2], x1v[3]);
            *(float4*)&g_x1[idx + 4] = make_float4(x1v[4], x1v[5], x1v[6], x1v[7]);
        }
        if (ACCM == 1 || ACCM == 2) {
            *(float4*)&accb[idx]     = make_float4(ao[0], ao[1], ao[2], ao[3]);
            *(float4*)&accb[idx + 4] = make_float4(ao[4], ao[5], ao[6], ao[7]);
        }
        if (ACCM == 3) {
            *(float4*)&finout[idx]     = make_float4(fo[0], fo[1], fo[2], fo[3]);
            *(float4*)&finout[idx + 4] = make_float4(fo[4], fo[5], fo[6], fo[7]);
        }
    }
}

extern "C" void kernel_launch(void* const* d_in, const int* in_sizes, int n_in,
                              void* d_out, int out_size)
{
    const float* x  = (const float*)d_in[0];   // [B, D]
    const float* Ws = (const float*)d_in[1];   // [L, D, D]
    const float* bs = (const float*)d_in[2];   // [L, D]
    const float* Wx = (const float*)d_in[3];   // [D, D]
    const float* bx = (const float*)d_in[4];   // [D]
    float* out = (float*)d_out;                // [2, B, D] : af then al

    dim3 gg(Dd / 128, Bsz / 128, NCHUNK);      // (16, 4, 4) = 256 CTAs
    dim3 bbk(256);

    // stage 1: x1 = x @ Wx + bx ; store raw x1; u0,s0 = lif(x1); af = s0
    gemm_lif_fused<false, false, true, 1><<<gg, bbk>>>(x, Wx, bx, -1, 0, nullptr);
    // t = 0, layer 1
    gemm_lif_fused<false, false, false, 0><<<gg, bbk>>>(nullptr, Ws + 0 * DD, bs + 0 * Dd, 0, 1, nullptr);
    // t = 0, layer 2 ; al = s2
    gemm_lif_fused<false, false, false, 1><<<gg, bbk>>>(nullptr, Ws + 1 * DD, bs + 1 * Dd, 1, 2, nullptr);

    for (int t = 1; t < TSTEPS; ++t) {
        const bool last = (t == TSTEPS - 1);
        // layer 0: u0 + s2 @ Ws[2] + bs[2] + x1 ; af update
        if (!last)
            gemm_lif_fused<true, true, false, 2><<<gg, bbk>>>(nullptr, Ws + 2 * DD, bs + 2 * Dd, 2, 0, nullptr);
        else
            gemm_lif_fused<true, true, false, 3><<<gg, bbk>>>(nullptr, Ws + 2 * DD, bs + 2 * Dd, 2, 0, out);
        // layer 1: u1 + s0 @ Ws[0] + bs[0]
        gemm_lif_fused<true, false, false, 0><<<gg, bbk>>>(nullptr, Ws + 0 * DD, bs + 0 * Dd, 0, 1, nullptr);
        // layer 2: u2 + s1 @ Ws[1] + bs[1] ; al update
        if (!last)
            gemm_lif_fused<true, false, false, 2><<<gg, bbk>>>(nullptr, Ws + 1 * DD, bs + 1 * Dd, 1, 2, nullptr);
        else
            gemm_lif_fused<true, false, false, 3><<<gg, bbk>>>(nullptr, Ws + 1 * DD, bs + 1 * Dd, 1, 2, out + BD);
    }
}